// round 16
// baseline (speedup 1.0000x reference)
#include <cuda_runtime.h>
#include <cuda_fp16.h>
#include <cstdint>
#include <cstddef>

// Problem constants
#define T_LEN 800
#define NB    32
#define LIN   4000
#define FEATC 320
#define KW    19
#define PADL  7
#define NSTATE 1024
#define NZ    5
#define CN    5120           // NSTATE * NZ
#define M_TOT (T_LEN * NB)   // 25600
#define KTOT  320            // single fp16 GEMM (no split)

// GEMM tiling: 128x128 block, 8 warps (2m x 4n), warp tile 64x32, BK=64
#define BM 128
#define BN 128
#define BK 64
#define NKT (KTOT / BK)      // 5
#define STAGES 3
#define A_STAGE 16384        // 128 rows * 128 B
#define B_STAGE 16384        // 128 rows * 128 B
#define GEMM_SMEM (STAGES * (A_STAGE + B_STAGE))   // 98304

#define N_MTILES (M_TOT / BM)   // 200
#define N_NTILES (CN / BN)      // 40
#define GEMM_TILES (N_MTILES * N_NTILES)  // 8000
#define GEMM_PBLKS 264          // persistent GEMM blocks (+32 scan = 296 = 2*148)

// Scan (256 threads, 4 states/thread)
#define RBUF 8
#define PFD  7
#define STEP_BYTES (CN * 2)    // 10240
#define GRAN (STEP_BYTES / 16) // 640
#define SCAN_SMEM (2 * NSTATE * 4 + 32 + RBUF * STEP_BYTES)   // 90144
#define FUSED_SMEM (SCAN_SMEM > GEMM_SMEM ? SCAN_SMEM : GEMM_SMEM)

// Scratch (no allocations allowed)
__device__ __half g_A[M_TOT * KTOT];          // [M, 320] fp16 tanh features
__device__ __half g_B[CN * KTOT];             // [N, 320] fp16 weights (K-major)
__device__ __half g_E[(size_t)M_TOT * CN];    // exp(scores), fp16
__device__ float g_logz_over_T[NB];
__device__ unsigned g_ready[N_MTILES];        // per-bm-tile completion counters

// ---------------------------------------------------------------------------
// helpers
// ---------------------------------------------------------------------------
__device__ __forceinline__ uint32_t smem_u32(const void* p) {
    uint32_t a;
    asm("{ .reg .u64 t; cvta.to.shared.u64 t, %1; cvt.u32.u64 %0, t; }"
        : "=r"(a) : "l"(p));
    return a;
}
__device__ __forceinline__ float fast_tanh(float x) {
    float r;
    asm("tanh.approx.f32 %0, %1;" : "=f"(r) : "f"(x));
    return r;
}
#define CP_ASYNC16(saddr, gptr)                                                \
    asm volatile("cp.async.cg.shared.global [%0], [%1], 16;"                   \
                 :: "r"(saddr), "l"(gptr) : "memory")
#define CP_COMMIT() asm volatile("cp.async.commit_group;" ::: "memory")
#define CP_WAIT(n)  asm volatile("cp.async.wait_group %0;" :: "n"(n) : "memory")

#define LDMATRIX_X4(r, addr)                                                   \
    asm volatile("ldmatrix.sync.aligned.m8n8.x4.shared.b16 {%0,%1,%2,%3}, [%4];" \
                 : "=r"((r)[0]), "=r"((r)[1]), "=r"((r)[2]), "=r"((r)[3])      \
                 : "r"(addr))

#define MMA16816(d, a, b0, b1)                                                 \
    asm volatile("mma.sync.aligned.m16n8k16.row.col.f32.f16.f16.f32 "          \
                 "{%0,%1,%2,%3}, {%4,%5,%6,%7}, {%8,%9}, {%0,%1,%2,%3};"       \
                 : "+f"((d)[0]), "+f"((d)[1]), "+f"((d)[2]), "+f"((d)[3])      \
                 : "r"((a)[0]), "r"((a)[1]), "r"((a)[2]), "r"((a)[3]),         \
                   "r"(b0), "r"(b1))

// acquire-spin until tile containing step t is fully written (40 bn blocks)
__device__ __forceinline__ void wait_tile(int tstep) {
    const unsigned* f = &g_ready[tstep >> 2];
    unsigned v;
    do {
        asm volatile("ld.acquire.gpu.global.u32 %0, [%1];"
                     : "=r"(v) : "l"(f) : "memory");
        if (v < (unsigned)N_NTILES) __nanosleep(128);
    } while (v < (unsigned)N_NTILES);
}

// ---------------------------------------------------------------------------
// Kernel 0: zero the tile-ready flags (every launch / graph replay)
// ---------------------------------------------------------------------------
__global__ void init_kernel() {
    if (threadIdx.x < N_MTILES) g_ready[threadIdx.x] = 0u;
}

// ---------------------------------------------------------------------------
// Kernel 1: strided conv + tanh -> g_A (fp16)
// ---------------------------------------------------------------------------
#define TCHUNK 16
#define XSEG ((TCHUNK - 1) * 5 + KW)   // 94

__global__ void conv_kernel(const float* __restrict__ x,
                            const float* __restrict__ w,
                            const float* __restrict__ b) {
    __shared__ float sw[FEATC * KW];
    __shared__ float sb[FEATC];
    __shared__ float sx[XSEG];

    const int n  = blockIdx.y;
    const int t0 = blockIdx.x * TCHUNK;
    const int tid = threadIdx.x;

    for (int i = tid; i < FEATC * KW; i += blockDim.x) sw[i] = w[i];
    if (tid < FEATC) sb[tid] = b[tid];
    const int base = t0 * 5 - PADL;
    for (int i = tid; i < XSEG; i += blockDim.x) {
        int gx = base + i;
        sx[i] = (gx >= 0 && gx < LIN) ? x[n * LIN + gx] : 0.0f;
    }
    __syncthreads();

    const int f = tid;
    float acc[TCHUNK];
#pragma unroll
    for (int i = 0; i < TCHUNK; i++) acc[i] = sb[f];
#pragma unroll
    for (int k = 0; k < KW; k++) {
        const float wk = sw[f * KW + k];
#pragma unroll
        for (int i = 0; i < TCHUNK; i++) acc[i] += wk * sx[i * 5 + k];
    }
#pragma unroll
    for (int i = 0; i < TCHUNK; i++) {
        const int row = (t0 + i) * NB + n;
        g_A[(size_t)row * KTOT + f] = __float2half(fast_tanh(acc[i]));
    }
}

// ---------------------------------------------------------------------------
// Kernel 1b: transpose lin_w [320,5120] -> g_B [5120, 320] fp16 (K-major)
// ---------------------------------------------------------------------------
__global__ void convb_kernel(const float* __restrict__ w) {
    int i = blockIdx.x * blockDim.x + threadIdx.x;   // over 320*5120
    if (i >= FEATC * CN) return;
    int f = i / CN;
    int c = i % CN;
    g_B[(size_t)c * KTOT + f] = __float2half(w[i]);
}

// ---------------------------------------------------------------------------
// Persistent GEMM: block p handles tiles p, p+264, ... as one continuous
// chunk stream through a 3-stage cp.async ring that never drains across
// tile boundaries. 128x128 tile, 8 warps, warp tile 64x32, BK=64.
// ---------------------------------------------------------------------------
__device__ __forceinline__ void load_chunk(int p, int c, int tid,
                                           uint32_t sA, uint32_t sB) {
    const int i  = c / NKT;
    const int kt = c - i * NKT;
    const int tau = p + i * GEMM_PBLKS;
    const int bm = tau / N_NTILES;
    const int bn = tau - bm * N_NTILES;
    const int stg = c % STAGES;
    const __half* gA = g_A + (size_t)bm * BM * KTOT + kt * BK;
    const __half* gB = g_B + (size_t)bn * BN * KTOT + kt * BK;
#pragma unroll
    for (int ii = 0; ii < 4; ii++) {
        int idx = tid + ii * 256;
        int row = idx >> 3, ch = idx & 7;
        uint32_t off = row * 128 + ((ch ^ (row & 7)) << 4);
        CP_ASYNC16(sA + stg * A_STAGE + off, gA + (size_t)row * KTOT + ch * 8);
        CP_ASYNC16(sB + stg * B_STAGE + off, gB + (size_t)row * KTOT + ch * 8);
    }
}

__device__ void gemm_body(int p, const float* __restrict__ lin_b,
                          char* smem) {
    const uint32_t sbase = smem_u32(smem);
    const uint32_t sA = sbase;
    const uint32_t sB = sbase + STAGES * A_STAGE;

    const int tid  = threadIdx.x;
    const int wid  = tid >> 5;
    const int lane = tid & 31;
    const int g = lane >> 2;
    const int t = lane & 3;
    const int warp_m = (wid & 1) * 64;
    const int warp_n = (wid >> 1) * 32;

    const int nt = (GEMM_TILES - p + GEMM_PBLKS - 1) / GEMM_PBLKS;
    const int nchunks = nt * NKT;

    float acc[4][4][4];
#pragma unroll
    for (int mi = 0; mi < 4; mi++)
#pragma unroll
        for (int ni = 0; ni < 4; ni++)
#pragma unroll
            for (int r = 0; r < 4; r++) acc[mi][ni][r] = 0.0f;

    // prologue: fill 2 stages (once per persistent block)
    load_chunk(p, 0, tid, sA, sB);
    CP_COMMIT();
    if (nchunks > 1) load_chunk(p, 1, tid, sA, sB);
    CP_COMMIT();

    for (int c = 0; c < nchunks; c++) {
        CP_WAIT(1);
        __syncthreads();

        if (c + 2 < nchunks) load_chunk(p, c + 2, tid, sA, sB);
        CP_COMMIT();

        const int stg = c % STAGES;
        const uint32_t aBase = sA + stg * A_STAGE;
        const uint32_t bBase = sB + stg * B_STAGE;

#pragma unroll
        for (int ks = 0; ks < 4; ks++) {     // 4 x k16 per BK=64
            uint32_t af[4][4];
#pragma unroll
            for (int mi = 0; mi < 4; mi++) {
                int m = warp_m + mi * 16 + ((lane >> 3) & 1) * 8 + (lane & 7);
                int chL = ks * 2 + (lane >> 4);
                uint32_t addr = aBase + m * 128 + ((chL ^ (m & 7)) << 4);
                LDMATRIX_X4(af[mi], addr);
            }
            uint32_t bf[4][2];
#pragma unroll
            for (int pq = 0; pq < 2; pq++) {
                int nrow = warp_n + pq * 16 + ((lane >> 4) & 1) * 8 + (lane & 7);
                int chL = ks * 2 + ((lane >> 3) & 1);
                uint32_t addr = bBase + nrow * 128 + ((chL ^ (nrow & 7)) << 4);
                uint32_t r[4];
                LDMATRIX_X4(r, addr);
                bf[2 * pq][0] = r[0];
                bf[2 * pq][1] = r[1];
                bf[2 * pq + 1][0] = r[2];
                bf[2 * pq + 1][1] = r[3];
            }
#pragma unroll
            for (int ni = 0; ni < 4; ni++)
#pragma unroll
                for (int mi = 0; mi < 4; mi++)
                    MMA16816(acc[mi][ni], af[mi], bf[ni][0], bf[ni][1]);
        }

        // tile boundary: epilogue + release, then reset accumulators
        const int i  = c / NKT;
        const int kt = c - i * NKT;
        if (kt == NKT - 1) {
            const int tau = p + i * GEMM_PBLKS;
            const int bm = tau / N_NTILES;
            const int bn = tau - bm * N_NTILES;
#pragma unroll
            for (int mi = 0; mi < 4; mi++) {
                const int row0 = bm * BM + warp_m + mi * 16 + g;
#pragma unroll
                for (int ni = 0; ni < 4; ni++) {
                    const int col = bn * BN + warp_n + ni * 8 + 2 * t;
                    const float2 bb = *(const float2*)(lin_b + col);
                    float v0 = 5.0f * fast_tanh(acc[mi][ni][0] + bb.x);
                    float v1 = 5.0f * fast_tanh(acc[mi][ni][1] + bb.y);
                    float v2 = 5.0f * fast_tanh(acc[mi][ni][2] + bb.x);
                    float v3 = 5.0f * fast_tanh(acc[mi][ni][3] + bb.y);
                    __half2 e01 = __floats2half2_rn(__expf(v0), __expf(v1));
                    __half2 e23 = __floats2half2_rn(__expf(v2), __expf(v3));
                    *(__half2*)(g_E + (size_t)row0 * CN + col) = e01;
                    *(__half2*)(g_E + (size_t)(row0 + 8) * CN + col) = e23;
                    acc[mi][ni][0] = 0.0f;
                    acc[mi][ni][1] = 0.0f;
                    acc[mi][ni][2] = 0.0f;
                    acc[mi][ni][3] = 0.0f;
                }
            }
            __threadfence();
            __syncthreads();
            if (tid == 0) atomicAdd(&g_ready[bm], 1u);
        }
    }
}

// ---------------------------------------------------------------------------
// Scan body: linear-domain forward scan on g_E, gated on tile readiness.
// 256 threads, 4 states/thread, 8-deep cp.async ring, renorm every 8 steps.
// ---------------------------------------------------------------------------
__device__ void scan_body(int n, char* dsm) {
    float* alpha = (float*)dsm;                      // [2][NSTATE]
    float* wred  = (float*)(dsm + 2 * NSTATE * 4);   // [8]
    char*  ms    = dsm + 2 * NSTATE * 4 + 32;        // [RBUF][STEP_BYTES]

    const int c = threadIdx.x;
    const int lane = c & 31;
    const int wrp = c >> 5;

    const char* gbase = (const char*)(g_E + (size_t)n * CN);
    const size_t tstr = (size_t)NB * CN * 2;

    const uint32_t ms0 = smem_u32(ms);

#pragma unroll
    for (int s = 0; s < PFD; s++) {
        if ((s & 3) == 0) wait_tile(s);
        const char* gp = gbase + (size_t)s * tstr;
        uint32_t sp = ms0 + s * STEP_BYTES;
        CP_ASYNC16(sp + c * 16, gp + c * 16);
        CP_ASYNC16(sp + (c + 256) * 16, gp + (c + 256) * 16);
        if (c < GRAN - 512)
            CP_ASYNC16(sp + (c + 512) * 16, gp + (c + 512) * 16);
        CP_COMMIT();
    }

    float a0 = 1.0f, a1 = 1.0f, a2 = 1.0f, a3 = 1.0f;
    alpha[c] = 1.0f;
    alpha[c + 256] = 1.0f;
    alpha[c + 512] = 1.0f;
    alpha[c + 768] = 1.0f;

    CP_WAIT(PFD - 1);
    __syncthreads();

    float offset = 0.0f;
    int cur = 0;

    for (int t = 0; t < T_LEN; t++) {
        const int ts = t + PFD;
        if (ts < T_LEN) {
            if ((ts & 3) == 0 || t == 0) wait_tile(ts);
            const char* gp = gbase + (size_t)ts * tstr;
            uint32_t sp = ms0 + (ts & (RBUF - 1)) * STEP_BYTES;
            CP_ASYNC16(sp + c * 16, gp + c * 16);
            CP_ASYNC16(sp + (c + 256) * 16, gp + (c + 256) * 16);
            if (c < GRAN - 512)
                CP_ASYNC16(sp + (c + 512) * 16, gp + (c + 512) * 16);
        }
        CP_COMMIT();

        const char* mp = ms + (t & (RBUF - 1)) * STEP_BYTES + c * 40;
        const uint2 w0 = *(const uint2*)(mp);
        const uint2 w1 = *(const uint2*)(mp + 8);
        const uint2 w2 = *(const uint2*)(mp + 16);
        const uint2 w3 = *(const uint2*)(mp + 24);
        const uint2 w4 = *(const uint2*)(mp + 32);

        const float2 e0 = __half22float2(*(const __half2*)&w0.x);
        const float2 e1 = __half22float2(*(const __half2*)&w0.y);
        const float2 e2 = __half22float2(*(const __half2*)&w1.x);
        const float2 e3 = __half22float2(*(const __half2*)&w1.y);
        const float2 e4 = __half22float2(*(const __half2*)&w2.x);
        const float2 e5 = __half22float2(*(const __half2*)&w2.y);
        const float2 e6 = __half22float2(*(const __half2*)&w3.x);
        const float2 e7 = __half22float2(*(const __half2*)&w3.y);
        const float2 e8 = __half22float2(*(const __half2*)&w4.x);
        const float2 e9 = __half22float2(*(const __half2*)&w4.y);

        const float* al = alpha + cur * NSTATE;
        const float p0 = al[c];
        const float p1 = al[c + 256];
        const float p2 = al[c + 512];
        const float p3 = al[c + 768];

        float r0 = e0.x * a0;
        r0 = fmaf(e0.y, p0, r0); r0 = fmaf(e1.x, p1, r0);
        r0 = fmaf(e1.y, p2, r0); r0 = fmaf(e2.x, p3, r0);

        float r1 = e2.y * a1;
        r1 = fmaf(e3.x, p0, r1); r1 = fmaf(e3.y, p1, r1);
        r1 = fmaf(e4.x, p2, r1); r1 = fmaf(e4.y, p3, r1);

        float r2 = e5.x * a2;
        r2 = fmaf(e5.y, p0, r2); r2 = fmaf(e6.x, p1, r2);
        r2 = fmaf(e6.y, p2, r2); r2 = fmaf(e7.x, p3, r2);

        float r3 = e7.y * a3;
        r3 = fmaf(e8.x, p0, r3); r3 = fmaf(e8.y, p1, r3);
        r3 = fmaf(e9.x, p2, r3); r3 = fmaf(e9.y, p3, r3);

        if ((t & 7) == 7) {
            float mx = fmaxf(fmaxf(r0, r1), fmaxf(r2, r3));
#pragma unroll
            for (int o = 16; o > 0; o >>= 1)
                mx = fmaxf(mx, __shfl_xor_sync(0xffffffffu, mx, o));
            if (lane == 0) wred[wrp] = mx;
            __syncthreads();
            float m = fmaxf(fmaxf(wred[0], wred[1]), fmaxf(wred[2], wred[3]));
            m = fmaxf(m, fmaxf(fmaxf(wred[4], wred[5]), fmaxf(wred[6], wred[7])));
            const uint32_t eb = (__float_as_uint(m) >> 23) & 0xffu;
            const float scale = __uint_as_float((254u - eb) << 23);
            r0 *= scale; r1 *= scale; r2 *= scale; r3 *= scale;
            offset += (float)((int)eb - 127);
        }

        a0 = r0; a1 = r1; a2 = r2; a3 = r3;
        *(float4*)(alpha + (cur ^ 1) * NSTATE + 4 * c) =
            make_float4(r0, r1, r2, r3);

        CP_WAIT(PFD - 1);
        __syncthreads();
        cur ^= 1;
    }

    float v = a0 + a1 + a2 + a3;
#pragma unroll
    for (int o = 16; o > 0; o >>= 1)
        v += __shfl_xor_sync(0xffffffffu, v, o);
    if (lane == 0) wred[wrp] = v;
    __syncthreads();
    if (c == 0) {
        float s = wred[0] + wred[1] + wred[2] + wred[3] +
                  wred[4] + wred[5] + wred[6] + wred[7];
        const float LN2 = 0.6931471805599453f;
        g_logz_over_T[n] = (logf(s) + offset * LN2) * (1.0f / (float)T_LEN);
    }
}

// ---------------------------------------------------------------------------
// Kernel 2: FUSED persistent gemm + scan. Blocks 0..31 scan; blocks 32..295
// are persistent GEMM workers.
// ---------------------------------------------------------------------------
__global__ __launch_bounds__(256, 2)
void fused_kernel(const float* __restrict__ lin_b) {
    extern __shared__ __align__(1024) char smem[];
    if (blockIdx.x < NB) {
        scan_body(blockIdx.x, smem);
    } else {
        gemm_body(blockIdx.x - NB, lin_b, smem);
    }
}

// ---------------------------------------------------------------------------
// Kernel 3: finalize — out = logf(g_E) - logZ/T. One block per (t,n) row.
// ---------------------------------------------------------------------------
__global__ void final_kernel(float* __restrict__ out) {
    const int row = blockIdx.x;             // t*NB + n
    const float s = g_logz_over_T[row & (NB - 1)];
    const __half2* e = (const __half2*)(g_E + (size_t)row * CN);
    float4* p = (float4*)(out + (size_t)row * CN);
#pragma unroll
    for (int j = threadIdx.x; j < CN / 4; j += 256) {
        float2 a = __half22float2(e[2 * j]);
        float2 b = __half22float2(e[2 * j + 1]);
        p[j] = make_float4(__logf(a.x) - s, __logf(a.y) - s,
                           __logf(b.x) - s, __logf(b.y) - s);
    }
}

// ---------------------------------------------------------------------------
extern "C" void kernel_launch(void* const* d_in, const int* in_sizes, int n_in,
                              void* d_out, int out_size) {
    const float* x      = (const float*)d_in[0];
    const float* conv_w = (const float*)d_in[1];
    const float* conv_b = (const float*)d_in[2];
    const float* lin_w  = (const float*)d_in[3];
    const float* lin_b  = (const float*)d_in[4];
    float* out = (float*)d_out;

    static bool attr_set = false;
    if (!attr_set) {
        cudaFuncSetAttribute(fused_kernel,
                             cudaFuncAttributeMaxDynamicSharedMemorySize,
                             FUSED_SMEM);
        attr_set = true;
    }

    init_kernel<<<1, 256>>>();
    conv_kernel<<<dim3(T_LEN / TCHUNK, NB), FEATC>>>(x, conv_w, conv_b);
    convb_kernel<<<(FEATC * CN + 255) / 256, 256>>>(lin_w);
    fused_kernel<<<NB + GEMM_PBLKS, 256, FUSED_SMEM>>>(lin_b);
    final_kernel<<<M_TOT, 256>>>(out);
}

// round 17
// speedup vs baseline: 1.0590x; 1.0590x over previous
#include <cuda_runtime.h>
#include <cuda_fp16.h>
#include <cstdint>
#include <cstddef>

// Problem constants
#define T_LEN 800
#define NB    32
#define LIN   4000
#define FEATC 320
#define KW    19
#define PADL  7
#define NSTATE 1024
#define NZ    5
#define CN    5120           // NSTATE * NZ
#define M_TOT (T_LEN * NB)   // 25600
#define KTOT  320            // single fp16 GEMM (no split)

// GEMM tiling: 128x128 block, 8 warps (2m x 4n), warp tile 64x32, BK=64
#define BM 128
#define BN 128
#define BK 64
#define NKT (KTOT / BK)      // 5
#define STAGES 3
#define A_STAGE 16384        // 128 rows * 128 B
#define B_STAGE 16384        // 128 rows * 128 B
#define GEMM_SMEM (STAGES * (A_STAGE + B_STAGE))   // 98304

#define N_MTILES (M_TOT / BM)   // 200
#define N_NTILES (CN / BN)      // 40
#define GEMM_BLOCKS (N_MTILES * N_NTILES)  // 8000

// Scan (256 threads, 4 states/thread)
#define RBUF 8
#define PFD  7
#define STEP_BYTES (CN * 2)    // 10240
#define GRAN (STEP_BYTES / 16) // 640
#define SCAN_SMEM (2 * NSTATE * 4 + 32 + RBUF * STEP_BYTES)   // 90144
#define FUSED_SMEM (SCAN_SMEM > GEMM_SMEM ? SCAN_SMEM : GEMM_SMEM)

// Setup kernel split: conv blocks then convb blocks
#define CONV_BLOCKS (T_LEN / 16 * NB)            // 1600 (TCHUNK=16)
#define CONVB_BLOCKS ((FEATC * CN + 319) / 320)  // 5120
#define SETUP_BLOCKS (CONV_BLOCKS + CONVB_BLOCKS)

// Scratch (no allocations allowed)
__device__ __half g_A[M_TOT * KTOT];          // [M, 320] fp16 tanh features
__device__ __half g_B[CN * KTOT];             // [N, 320] fp16 weights (K-major)
__device__ __half g_E[(size_t)M_TOT * CN];    // exp(scores), fp16
__device__ float g_logz_over_T[NB];
__device__ unsigned g_ready[N_MTILES];        // per-bm-tile completion counters

// ---------------------------------------------------------------------------
// helpers
// ---------------------------------------------------------------------------
__device__ __forceinline__ uint32_t smem_u32(const void* p) {
    uint32_t a;
    asm("{ .reg .u64 t; cvta.to.shared.u64 t, %1; cvt.u32.u64 %0, t; }"
        : "=r"(a) : "l"(p));
    return a;
}
__device__ __forceinline__ float fast_tanh(float x) {
    float r;
    asm("tanh.approx.f32 %0, %1;" : "=f"(r) : "f"(x));
    return r;
}
#define CP_ASYNC16(saddr, gptr)                                                \
    asm volatile("cp.async.cg.shared.global [%0], [%1], 16;"                   \
                 :: "r"(saddr), "l"(gptr) : "memory")
#define CP_COMMIT() asm volatile("cp.async.commit_group;" ::: "memory")
#define CP_WAIT(n)  asm volatile("cp.async.wait_group %0;" :: "n"(n) : "memory")

#define LDMATRIX_X4(r, addr)                                                   \
    asm volatile("ldmatrix.sync.aligned.m8n8.x4.shared.b16 {%0,%1,%2,%3}, [%4];" \
                 : "=r"((r)[0]), "=r"((r)[1]), "=r"((r)[2]), "=r"((r)[3])      \
                 : "r"(addr))

#define MMA16816(d, a, b0, b1)                                                 \
    asm volatile("mma.sync.aligned.m16n8k16.row.col.f32.f16.f16.f32 "          \
                 "{%0,%1,%2,%3}, {%4,%5,%6,%7}, {%8,%9}, {%0,%1,%2,%3};"       \
                 : "+f"((d)[0]), "+f"((d)[1]), "+f"((d)[2]), "+f"((d)[3])      \
                 : "r"((a)[0]), "r"((a)[1]), "r"((a)[2]), "r"((a)[3]),         \
                   "r"(b0), "r"(b1))

// acquire-spin until tile containing step t is fully written (40 bn blocks)
__device__ __forceinline__ void wait_tile(int tstep) {
    const unsigned* f = &g_ready[tstep >> 2];
    unsigned v;
    do {
        asm volatile("ld.acquire.gpu.global.u32 %0, [%1];"
                     : "=r"(v) : "l"(f) : "memory");
        if (v < (unsigned)N_NTILES) __nanosleep(128);
    } while (v < (unsigned)N_NTILES);
}

// ---------------------------------------------------------------------------
// Kernel 1: SETUP — conv(+tanh) for blocks [0, CONV_BLOCKS), weight
// transpose for blocks [CONV_BLOCKS, ...). Block 0 also zeroes g_ready.
// 320 threads per block.
// ---------------------------------------------------------------------------
#define TCHUNK 16
#define XSEG ((TCHUNK - 1) * 5 + KW)   // 94

__global__ void setup_kernel(const float* __restrict__ x,
                             const float* __restrict__ w,
                             const float* __restrict__ b,
                             const float* __restrict__ lin_w) {
    const int tid = threadIdx.x;

    if (blockIdx.x >= CONV_BLOCKS) {
        // ---- weight transpose: lin_w [320,5120] -> g_B [5120,320] fp16 ----
        int i = (blockIdx.x - CONV_BLOCKS) * 320 + tid;
        if (i < FEATC * CN) {
            int f = i / CN;
            int c = i % CN;
            g_B[(size_t)c * KTOT + f] = __float2half(lin_w[i]);
        }
        return;
    }

    if (blockIdx.x == 0 && tid < N_MTILES) g_ready[tid] = 0u;

    // ---- conv ----
    __shared__ float sw[FEATC * KW];
    __shared__ float sb[FEATC];
    __shared__ float sx[XSEG];

    const int n  = blockIdx.x & (NB - 1);          // CONV_BLOCKS = 50*32
    const int t0 = (blockIdx.x >> 5) * TCHUNK;

    for (int i = tid; i < FEATC * KW; i += blockDim.x) sw[i] = w[i];
    if (tid < FEATC) sb[tid] = b[tid];
    const int base = t0 * 5 - PADL;
    for (int i = tid; i < XSEG; i += blockDim.x) {
        int gx = base + i;
        sx[i] = (gx >= 0 && gx < LIN) ? x[n * LIN + gx] : 0.0f;
    }
    __syncthreads();

    const int f = tid;
    float acc[TCHUNK];
#pragma unroll
    for (int i = 0; i < TCHUNK; i++) acc[i] = sb[f];
#pragma unroll
    for (int k = 0; k < KW; k++) {
        const float wk = sw[f * KW + k];
#pragma unroll
        for (int i = 0; i < TCHUNK; i++) acc[i] += wk * sx[i * 5 + k];
    }
#pragma unroll
    for (int i = 0; i < TCHUNK; i++) {
        const int row = (t0 + i) * NB + n;
        g_A[(size_t)row * KTOT + f] = __float2half(fast_tanh(acc[i]));
    }
}

// ---------------------------------------------------------------------------
// GEMM body (HMMA fp16, K=320, 128x128 tile, 8 warps, warp tile 64x32,
// BK=64, 3-stage cp.async, 256 threads). Rows are 128 B with standard
// chunk ^= (row&7) swizzle. Writes exp(scores) fp16 to g_E only.
// ---------------------------------------------------------------------------
__device__ void gemm_body(int gbid, const float* __restrict__ lin_b,
                          char* smem) {
    const uint32_t sbase = smem_u32(smem);
    const uint32_t sA = sbase;
    const uint32_t sB = sbase + STAGES * A_STAGE;

    const int tid  = threadIdx.x;
    const int wid  = tid >> 5;
    const int lane = tid & 31;
    const int g = lane >> 2;
    const int t = lane & 3;
    const int warp_m = (wid & 1) * 64;
    const int warp_n = (wid >> 1) * 32;
    const int bm = gbid / N_NTILES;   // increasing-t order
    const int bn = gbid % N_NTILES;

    const __half* gA = g_A + (size_t)bm * BM * KTOT;
    const __half* gB = g_B + (size_t)bn * BN * KTOT;

#define LOAD_STAGE(stg, kt)                                                    \
    do {                                                                       \
        _Pragma("unroll")                                                      \
        for (int i = 0; i < 4; i++) {                                          \
            int idx = tid + i * 256;                                           \
            int row = idx >> 3, ch = idx & 7;                                  \
            const __half* gpa = gA + (size_t)row * KTOT + (kt) * BK + ch * 8;  \
            uint32_t spa = sA + (stg) * A_STAGE + row * 128 +                  \
                           ((ch ^ (row & 7)) << 4);                            \
            CP_ASYNC16(spa, gpa);                                              \
            const __half* gpb = gB + (size_t)row * KTOT + (kt) * BK + ch * 8;  \
            uint32_t spb = sB + (stg) * B_STAGE + row * 128 +                  \
                           ((ch ^ (row & 7)) << 4);                            \
            CP_ASYNC16(spb, gpb);                                              \
        }                                                                      \
    } while (0)

    float acc[4][4][4];
#pragma unroll
    for (int mi = 0; mi < 4; mi++)
#pragma unroll
        for (int ni = 0; ni < 4; ni++)
#pragma unroll
            for (int r = 0; r < 4; r++) acc[mi][ni][r] = 0.0f;

#pragma unroll
    for (int s = 0; s < STAGES - 1; s++) {
        LOAD_STAGE(s, s);
        CP_COMMIT();
    }

    for (int kt = 0; kt < NKT; kt++) {
        CP_WAIT(STAGES - 2);
        __syncthreads();

        const int nk = kt + STAGES - 1;
        if (nk < NKT) LOAD_STAGE(nk % STAGES, nk);
        CP_COMMIT();

        const uint32_t aBase = sA + (kt % STAGES) * A_STAGE;
        const uint32_t bBase = sB + (kt % STAGES) * B_STAGE;

#pragma unroll
        for (int ks = 0; ks < 4; ks++) {     // 4 x k16 per BK=64
            uint32_t af[4][4];
#pragma unroll
            for (int mi = 0; mi < 4; mi++) {
                int m = warp_m + mi * 16 + ((lane >> 3) & 1) * 8 + (lane & 7);
                int chL = ks * 2 + (lane >> 4);
                uint32_t addr = aBase + m * 128 + ((chL ^ (m & 7)) << 4);
                LDMATRIX_X4(af[mi], addr);
            }
            uint32_t bf[4][2];
#pragma unroll
            for (int p = 0; p < 2; p++) {
                int nrow = warp_n + p * 16 + ((lane >> 4) & 1) * 8 + (lane & 7);
                int chL = ks * 2 + ((lane >> 3) & 1);
                uint32_t addr = bBase + nrow * 128 + ((chL ^ (nrow & 7)) << 4);
                uint32_t r[4];
                LDMATRIX_X4(r, addr);
                bf[2 * p][0] = r[0];
                bf[2 * p][1] = r[1];
                bf[2 * p + 1][0] = r[2];
                bf[2 * p + 1][1] = r[3];
            }
#pragma unroll
            for (int ni = 0; ni < 4; ni++)
#pragma unroll
                for (int mi = 0; mi < 4; mi++)
                    MMA16816(acc[mi][ni], af[mi], bf[ni][0], bf[ni][1]);
        }
    }

    // ---- epilogue: bias + 5*tanh, store exp(scores) fp16 ONLY ----
#pragma unroll
    for (int mi = 0; mi < 4; mi++) {
        const int row0 = bm * BM + warp_m + mi * 16 + g;
#pragma unroll
        for (int ni = 0; ni < 4; ni++) {
            const int col = bn * BN + warp_n + ni * 8 + 2 * t;
            const float2 bb = *(const float2*)(lin_b + col);
            float v0 = 5.0f * fast_tanh(acc[mi][ni][0] + bb.x);
            float v1 = 5.0f * fast_tanh(acc[mi][ni][1] + bb.y);
            float v2 = 5.0f * fast_tanh(acc[mi][ni][2] + bb.x);
            float v3 = 5.0f * fast_tanh(acc[mi][ni][3] + bb.y);
            __half2 e01 = __floats2half2_rn(__expf(v0), __expf(v1));
            __half2 e23 = __floats2half2_rn(__expf(v2), __expf(v3));
            *(__half2*)(g_E + (size_t)row0 * CN + col) = e01;
            *(__half2*)(g_E + (size_t)(row0 + 8) * CN + col) = e23;
        }
    }

    // release this tile
    __threadfence();
    __syncthreads();
    if (tid == 0) atomicAdd(&g_ready[bm], 1u);
}

// ---------------------------------------------------------------------------
// Scan body: linear-domain forward scan on g_E, gated on tile readiness.
// 256 threads, 4 states/thread, 8-deep cp.async ring, renorm every 8 steps.
// ---------------------------------------------------------------------------
__device__ void scan_body(int n, char* dsm) {
    float* alpha = (float*)dsm;                      // [2][NSTATE]
    float* wred  = (float*)(dsm + 2 * NSTATE * 4);   // [8]
    char*  ms    = dsm + 2 * NSTATE * 4 + 32;        // [RBUF][STEP_BYTES]

    const int c = threadIdx.x;
    const int lane = c & 31;
    const int wrp = c >> 5;

    const char* gbase = (const char*)(g_E + (size_t)n * CN);
    const size_t tstr = (size_t)NB * CN * 2;

    const uint32_t ms0 = smem_u32(ms);

#pragma unroll
    for (int s = 0; s < PFD; s++) {
        if ((s & 3) == 0) wait_tile(s);
        const char* gp = gbase + (size_t)s * tstr;
        uint32_t sp = ms0 + s * STEP_BYTES;
        CP_ASYNC16(sp + c * 16, gp + c * 16);
        CP_ASYNC16(sp + (c + 256) * 16, gp + (c + 256) * 16);
        if (c < GRAN - 512)
            CP_ASYNC16(sp + (c + 512) * 16, gp + (c + 512) * 16);
        CP_COMMIT();
    }

    float a0 = 1.0f, a1 = 1.0f, a2 = 1.0f, a3 = 1.0f;
    alpha[c] = 1.0f;
    alpha[c + 256] = 1.0f;
    alpha[c + 512] = 1.0f;
    alpha[c + 768] = 1.0f;

    CP_WAIT(PFD - 1);
    __syncthreads();

    float offset = 0.0f;
    int cur = 0;

    for (int t = 0; t < T_LEN; t++) {
        const int ts = t + PFD;
        if (ts < T_LEN) {
            if ((ts & 3) == 0 || t == 0) wait_tile(ts);
            const char* gp = gbase + (size_t)ts * tstr;
            uint32_t sp = ms0 + (ts & (RBUF - 1)) * STEP_BYTES;
            CP_ASYNC16(sp + c * 16, gp + c * 16);
            CP_ASYNC16(sp + (c + 256) * 16, gp + (c + 256) * 16);
            if (c < GRAN - 512)
                CP_ASYNC16(sp + (c + 512) * 16, gp + (c + 512) * 16);
        }
        CP_COMMIT();

        const char* mp = ms + (t & (RBUF - 1)) * STEP_BYTES + c * 40;
        const uint2 w0 = *(const uint2*)(mp);
        const uint2 w1 = *(const uint2*)(mp + 8);
        const uint2 w2 = *(const uint2*)(mp + 16);
        const uint2 w3 = *(const uint2*)(mp + 24);
        const uint2 w4 = *(const uint2*)(mp + 32);

        const float2 e0 = __half22float2(*(const __half2*)&w0.x);
        const float2 e1 = __half22float2(*(const __half2*)&w0.y);
        const float2 e2 = __half22float2(*(const __half2*)&w1.x);
        const float2 e3 = __half22float2(*(const __half2*)&w1.y);
        const float2 e4 = __half22float2(*(const __half2*)&w2.x);
        const float2 e5 = __half22float2(*(const __half2*)&w2.y);
        const float2 e6 = __half22float2(*(const __half2*)&w3.x);
        const float2 e7 = __half22float2(*(const __half2*)&w3.y);
        const float2 e8 = __half22float2(*(const __half2*)&w4.x);
        const float2 e9 = __half22float2(*(const __half2*)&w4.y);

        const float* al = alpha + cur * NSTATE;
        const float p0 = al[c];
        const float p1 = al[c + 256];
        const float p2 = al[c + 512];
        const float p3 = al[c + 768];

        float r0 = e0.x * a0;
        r0 = fmaf(e0.y, p0, r0); r0 = fmaf(e1.x, p1, r0);
        r0 = fmaf(e1.y, p2, r0); r0 = fmaf(e2.x, p3, r0);

        float r1 = e2.y * a1;
        r1 = fmaf(e3.x, p0, r1); r1 = fmaf(e3.y, p1, r1);
        r1 = fmaf(e4.x, p2, r1); r1 = fmaf(e4.y, p3, r1);

        float r2 = e5.x * a2;
        r2 = fmaf(e5.y, p0, r2); r2 = fmaf(e6.x, p1, r2);
        r2 = fmaf(e6.y, p2, r2); r2 = fmaf(e7.x, p3, r2);

        float r3 = e7.y * a3;
        r3 = fmaf(e8.x, p0, r3); r3 = fmaf(e8.y, p1, r3);
        r3 = fmaf(e9.x, p2, r3); r3 = fmaf(e9.y, p3, r3);

        if ((t & 7) == 7) {
            float mx = fmaxf(fmaxf(r0, r1), fmaxf(r2, r3));
#pragma unroll
            for (int o = 16; o > 0; o >>= 1)
                mx = fmaxf(mx, __shfl_xor_sync(0xffffffffu, mx, o));
            if (lane == 0) wred[wrp] = mx;
            __syncthreads();
            float m = fmaxf(fmaxf(wred[0], wred[1]), fmaxf(wred[2], wred[3]));
            m = fmaxf(m, fmaxf(fmaxf(wred[4], wred[5]), fmaxf(wred[6], wred[7])));
            const uint32_t eb = (__float_as_uint(m) >> 23) & 0xffu;
            const float scale = __uint_as_float((254u - eb) << 23);
            r0 *= scale; r1 *= scale; r2 *= scale; r3 *= scale;
            offset += (float)((int)eb - 127);
        }

        a0 = r0; a1 = r1; a2 = r2; a3 = r3;
        *(float4*)(alpha + (cur ^ 1) * NSTATE + 4 * c) =
            make_float4(r0, r1, r2, r3);

        CP_WAIT(PFD - 1);
        __syncthreads();
        cur ^= 1;
    }

    float v = a0 + a1 + a2 + a3;
#pragma unroll
    for (int o = 16; o > 0; o >>= 1)
        v += __shfl_xor_sync(0xffffffffu, v, o);
    if (lane == 0) wred[wrp] = v;
    __syncthreads();
    if (c == 0) {
        float s = wred[0] + wred[1] + wred[2] + wred[3] +
                  wred[4] + wred[5] + wred[6] + wred[7];
        const float LN2 = 0.6931471805599453f;
        g_logz_over_T[n] = (logf(s) + offset * LN2) * (1.0f / (float)T_LEN);
    }
}

// ---------------------------------------------------------------------------
// Kernel 2: FUSED gemm + scan. Blocks 0..31 scan; blocks 32.. run the GEMM
// in increasing-t tile order.
// ---------------------------------------------------------------------------
__global__ __launch_bounds__(256, 2)
void fused_kernel(const float* __restrict__ lin_b) {
    extern __shared__ __align__(1024) char smem[];
    if (blockIdx.x < NB) {
        scan_body(blockIdx.x, smem);
    } else {
        gemm_body(blockIdx.x - NB, lin_b, smem);
    }
}

// ---------------------------------------------------------------------------
// Kernel 3: finalize — out = logf(g_E) - logZ/T. One block per 2 rows.
// ---------------------------------------------------------------------------
__global__ __launch_bounds__(512, 4)
void final_kernel(float* __restrict__ out) {
    const int row = blockIdx.x * 2 + (threadIdx.x >> 8);   // t*NB + n
    const int tid = threadIdx.x & 255;
    const float s = g_logz_over_T[row & (NB - 1)];
    const __half2* e = (const __half2*)(g_E + (size_t)row * CN);
    float4* p = (float4*)(out + (size_t)row * CN);
#pragma unroll
    for (int j = tid; j < CN / 4; j += 256) {
        float2 a = __half22float2(e[2 * j]);
        float2 b = __half22float2(e[2 * j + 1]);
        p[j] = make_float4(__logf(a.x) - s, __logf(a.y) - s,
                           __logf(b.x) - s, __logf(b.y) - s);
    }
}

// ---------------------------------------------------------------------------
extern "C" void kernel_launch(void* const* d_in, const int* in_sizes, int n_in,
                              void* d_out, int out_size) {
    const float* x      = (const float*)d_in[0];
    const float* conv_w = (const float*)d_in[1];
    const float* conv_b = (const float*)d_in[2];
    const float* lin_w  = (const float*)d_in[3];
    const float* lin_b  = (const float*)d_in[4];
    float* out = (float*)d_out;

    static bool attr_set = false;
    if (!attr_set) {
        cudaFuncSetAttribute(fused_kernel,
                             cudaFuncAttributeMaxDynamicSharedMemorySize,
                             FUSED_SMEM);
        attr_set = true;
    }

    setup_kernel<<<SETUP_BLOCKS, 320>>>(x, conv_w, conv_b, lin_w);
    fused_kernel<<<NB + GEMM_BLOCKS, 256, FUSED_SMEM>>>(lin_b);
    final_kernel<<<M_TOT / 2, 512>>>(out);
}